// round 5
// baseline (speedup 1.0000x reference)
#include <cuda_runtime.h>

#define H_IMG 512
#define W_IMG 512
#define NMAX  2048
#define TILE  16
#define TX_N  (W_IMG / TILE)   /* 32 */
#define TY_N  (H_IMG / TILE)   /* 32 */
#define NTILES (TX_N * TY_N)   /* 1024 */

#define TWO_PI_F        6.28318530717958647692f
#define LOG2E_F         1.44269504088896340736f
#define LOG2_ALPHA_MIN  -7.99435344f   /* log2(1/255) */
#define ALPHA_MAX_F     0.999f

// Per-gaussian precomputed parameters
__device__ float4 g_P0[NMAX];          // mx, my, A(=0.5*c0), B(=0.5*c2)
__device__ float4 g_P1[NMAX];          // C(=c1), L(=log2(op)), fr, fg
__device__ float  g_FB[NMAX];          // fb
// Per-tile gaussian lists
__device__ int    g_tile_cnt[NTILES];          // zero at load; render re-zeroes
__device__ int    g_tile_list[NTILES][NMAX];   // 8 MB static scratch

// One WARP per gaussian: all lanes redundantly compute params (broadcast loads),
// lane 0 writes them, then all 32 lanes cooperatively test candidate tiles.
__global__ __launch_bounds__(256)
void prep_bin_kernel(const float* __restrict__ xyz,
                     const float* __restrict__ scaling,
                     const float* __restrict__ rot,
                     const float* __restrict__ feat,
                     const float* __restrict__ opac,
                     int N)
{
    int warp = (blockIdx.x * blockDim.x + threadIdx.x) >> 5;
    int lane = threadIdx.x & 31;
    int i = warp;
    if (i >= N) return;

    float theta = (1.0f / (1.0f + expf(-rot[i]))) * TWO_PI_F;
    float s0 = fabsf(scaling[2*i + 0]); s0 *= s0;
    float s1 = fabsf(scaling[2*i + 1]); s1 *= s1;
    float cs = cosf(theta);
    float sn = sinf(theta);

    float a = cs*cs*s0 + sn*sn*s1;
    float b = cs*sn*(s0 - s1);
    float c = sn*sn*s0 + cs*cs*s1;
    float inv_det = 1.0f / (a*c - b*b);
    float c0 =  c * inv_det;
    float c1 = -b * inv_det;
    float c2 =  a * inv_det;

    float mx = 0.5f * ((xyz[2*i + 0] + 1.0f) * (float)W_IMG - 1.0f);
    float my = 0.5f * ((xyz[2*i + 1] + 1.0f) * (float)H_IMG - 1.0f);

    float op = opac[i];
    float L  = log2f(op);                 // alpha = 2^(L - sigma*log2e)
    float lnthr = logf(op * 255.0f);      // contributes iff sigma <= lnthr
    float smax  = fmaxf(s0, s1);          // lambda_max(Sigma) upper bound
    float r2 = (lnthr > 0.0f) ? (2.0f * smax * lnthr) : -1.0f;

    if (lane == 0) {
        g_P0[i] = make_float4(mx, my, 0.5f * c0, 0.5f * c2);
        g_P1[i] = make_float4(c1, L, feat[3*i + 0], feat[3*i + 1]);
        g_FB[i] = feat[3*i + 2];
    }

    if (r2 <= 0.0f) return;
    float r = sqrtf(r2);

    int tx_lo = max(0,        (int)floorf((mx - r) * (1.0f / TILE)));
    int tx_hi = min(TX_N - 1, (int)floorf((mx + r) * (1.0f / TILE)));
    int ty_lo = max(0,        (int)floorf((my - r) * (1.0f / TILE)));
    int ty_hi = min(TY_N - 1, (int)floorf((my + r) * (1.0f / TILE)));
    if (tx_hi < tx_lo || ty_hi < ty_lo) return;

    int w = tx_hi - tx_lo + 1;
    int cand = w * (ty_hi - ty_lo + 1);

    for (int sidx = lane; sidx < cand; sidx += 32) {
        int tx = tx_lo + (sidx % w);
        int ty = ty_lo + (sidx / w);
        float bx0 = (float)(tx * TILE);
        float by0 = (float)(ty * TILE);
        float dxb = fmaxf(0.0f, fmaxf(bx0 - mx, mx - (bx0 + (TILE - 1))));
        float dyb = fmaxf(0.0f, fmaxf(by0 - my, my - (by0 + (TILE - 1))));
        if (fmaf(dxb, dxb, dyb * dyb) <= r2) {
            int t = ty * TX_N + tx;
            int pos = atomicAdd(&g_tile_cnt[t], 1);
            g_tile_list[t][pos] = i;
        }
    }
}

// 256 threads = 4 groups x 64. Each group renders the full 16x16 tile as
// 2x2 quads (4 px/thread) but processes only gaussians j = g, g+4, g+8, ...
// Partial sums combined via shared memory in fixed order (deterministic).
__global__ __launch_bounds__(256, 4)
void render_kernel(float* __restrict__ out)
{
    __shared__ int   s_list[NMAX];            // 8 KB
    __shared__ float s_red[3 * 64 * 13];      // ~10 KB, stride 13 => no bank conflicts

    const int tid = threadIdx.x;
    const int g   = tid >> 6;        // group 0..3
    const int t64 = tid & 63;
    const int tx  = t64 & 7;         // 0..7
    const int ty  = t64 >> 3;        // 0..7

    const int tile = blockIdx.y * TX_N + blockIdx.x;
    const int px0 = blockIdx.x * TILE + tx;
    const int py0 = blockIdx.y * TILE + ty;
    const float fx0 = (float)px0;
    const float fy0 = (float)py0;

    const int cnt = g_tile_cnt[tile];

    for (int k = tid; k < cnt; k += 256) s_list[k] = g_tile_list[tile][k];
    __syncthreads();

    float a00r = 0.0f, a00g = 0.0f, a00b = 0.0f;
    float a10r = 0.0f, a10g = 0.0f, a10b = 0.0f;
    float a01r = 0.0f, a01g = 0.0f, a01b = 0.0f;
    float a11r = 0.0f, a11g = 0.0f, a11b = 0.0f;

    // software-pipelined: prefetch next gaussian's params during current math
    int j = g;
    float4 Q0, Q1; float qb;
    if (j < cnt) {
        int idx = s_list[j];
        Q0 = g_P0[idx]; Q1 = g_P1[idx]; qb = g_FB[idx];
    }
    while (j < cnt) {
        float4 P0c = Q0; float4 P1c = Q1; float qbc = qb;
        j += 4;
        if (j < cnt) {
            int idx = s_list[j];
            Q0 = g_P0[idx]; Q1 = g_P1[idx]; qb = g_FB[idx];
        }

        float dx0 = fx0 - P0c.x;
        float dx1 = dx0 + 8.0f;
        float dy0 = fy0 - P0c.y;
        float dy1 = dy0 + 8.0f;

        float adx0 = P0c.z * dx0;            // A*dx (shared per column)
        float adx1 = P0c.z * dx1;
        float bdy0 = (P0c.w * dy0) * dy0;    // B*dy^2 (shared per row)
        float bdy1 = (P0c.w * dy1) * dy1;

        // sigma = (C*dy + A*dx)*dx + B*dy^2 ; arg = L - sigma*log2e
        float t00 = fmaf(P1c.x, dy0, adx0);
        float t10 = fmaf(P1c.x, dy0, adx1);
        float t01 = fmaf(P1c.x, dy1, adx0);
        float t11 = fmaf(P1c.x, dy1, adx1);
        float s00 = fmaf(t00, dx0, bdy0);
        float s10 = fmaf(t10, dx1, bdy0);
        float s01 = fmaf(t01, dx0, bdy1);
        float s11 = fmaf(t11, dx1, bdy1);
        float g00 = fmaf(s00, -LOG2E_F, P1c.y);
        float g10 = fmaf(s10, -LOG2E_F, P1c.y);
        float g01 = fmaf(s01, -LOG2E_F, P1c.y);
        float g11 = fmaf(s11, -LOG2E_F, P1c.y);

        float e00, e10, e01, e11;
        asm("ex2.approx.ftz.f32 %0, %1;" : "=f"(e00) : "f"(g00));
        asm("ex2.approx.ftz.f32 %0, %1;" : "=f"(e10) : "f"(g10));
        asm("ex2.approx.ftz.f32 %0, %1;" : "=f"(e01) : "f"(g01));
        asm("ex2.approx.ftz.f32 %0, %1;" : "=f"(e11) : "f"(g11));
        e00 = fminf(e00, ALPHA_MAX_F);
        e10 = fminf(e10, ALPHA_MAX_F);
        e01 = fminf(e01, ALPHA_MAX_F);
        e11 = fminf(e11, ALPHA_MAX_F);

        if (g00 >= LOG2_ALPHA_MIN) {
            a00r = fmaf(e00, P1c.z, a00r);
            a00g = fmaf(e00, P1c.w, a00g);
            a00b = fmaf(e00, qbc,   a00b);
        }
        if (g10 >= LOG2_ALPHA_MIN) {
            a10r = fmaf(e10, P1c.z, a10r);
            a10g = fmaf(e10, P1c.w, a10g);
            a10b = fmaf(e10, qbc,   a10b);
        }
        if (g01 >= LOG2_ALPHA_MIN) {
            a01r = fmaf(e01, P1c.z, a01r);
            a01g = fmaf(e01, P1c.w, a01g);
            a01b = fmaf(e01, qbc,   a01b);
        }
        if (g11 >= LOG2_ALPHA_MIN) {
            a11r = fmaf(e11, P1c.z, a11r);
            a11g = fmaf(e11, P1c.w, a11g);
            a11b = fmaf(e11, qbc,   a11b);
        }
    }

    // combine partial sums: groups 1-3 publish, group 0 adds in fixed order
    if (g > 0) {
        float* dst = &s_red[((g - 1) * 64 + t64) * 13];
        dst[0]  = a00r; dst[1]  = a00g; dst[2]  = a00b;
        dst[3]  = a10r; dst[4]  = a10g; dst[5]  = a10b;
        dst[6]  = a01r; dst[7]  = a01g; dst[8]  = a01b;
        dst[9]  = a11r; dst[10] = a11g; dst[11] = a11b;
    }
    __syncthreads();

    if (g == 0) {
        #pragma unroll
        for (int gg = 0; gg < 3; ++gg) {
            const float* src = &s_red[(gg * 64 + t64) * 13];
            a00r += src[0];  a00g += src[1];  a00b += src[2];
            a10r += src[3];  a10g += src[4];  a10b += src[5];
            a01r += src[6];  a01g += src[7];  a01b += src[8];
            a11r += src[9];  a11g += src[10]; a11b += src[11];
        }

        const int px1 = px0 + 8;
        const int py1 = py0 + 8;
        // out layout: [1, 3, H, W]
        out[(0 * H_IMG + py0) * W_IMG + px0] = fminf(fmaxf(a00r, 0.0f), 1.0f);
        out[(0 * H_IMG + py0) * W_IMG + px1] = fminf(fmaxf(a10r, 0.0f), 1.0f);
        out[(0 * H_IMG + py1) * W_IMG + px0] = fminf(fmaxf(a01r, 0.0f), 1.0f);
        out[(0 * H_IMG + py1) * W_IMG + px1] = fminf(fmaxf(a11r, 0.0f), 1.0f);
        out[(1 * H_IMG + py0) * W_IMG + px0] = fminf(fmaxf(a00g, 0.0f), 1.0f);
        out[(1 * H_IMG + py0) * W_IMG + px1] = fminf(fmaxf(a10g, 0.0f), 1.0f);
        out[(1 * H_IMG + py1) * W_IMG + px0] = fminf(fmaxf(a01g, 0.0f), 1.0f);
        out[(1 * H_IMG + py1) * W_IMG + px1] = fminf(fmaxf(a11g, 0.0f), 1.0f);
        out[(2 * H_IMG + py0) * W_IMG + px0] = fminf(fmaxf(a00b, 0.0f), 1.0f);
        out[(2 * H_IMG + py0) * W_IMG + px1] = fminf(fmaxf(a10b, 0.0f), 1.0f);
        out[(2 * H_IMG + py1) * W_IMG + px0] = fminf(fmaxf(a01b, 0.0f), 1.0f);
        out[(2 * H_IMG + py1) * W_IMG + px1] = fminf(fmaxf(a11b, 0.0f), 1.0f);

        if (t64 == 0) g_tile_cnt[tile] = 0;   // leave zeroed for next launch
    }
}

extern "C" void kernel_launch(void* const* d_in, const int* in_sizes, int n_in,
                              void* d_out, int out_size)
{
    const float* xyz     = (const float*)d_in[0];
    const float* scaling = (const float*)d_in[1];
    const float* rot     = (const float*)d_in[2];
    const float* feat    = (const float*)d_in[3];
    const float* opac    = (const float*)d_in[4];
    float* out = (float*)d_out;

    int N = in_sizes[0] / 2;
    if (N > NMAX) N = NMAX;

    // one warp per gaussian
    prep_bin_kernel<<<(N * 32 + 255) / 256, 256>>>(xyz, scaling, rot, feat, opac, N);

    dim3 grid(TX_N, TY_N);
    render_kernel<<<grid, 256>>>(out);
}

// round 6
// speedup vs baseline: 1.0785x; 1.0785x over previous
#include <cuda_runtime.h>

#define H_IMG 512
#define W_IMG 512
#define NMAX  2048
#define TILE  16
#define TX_N  (W_IMG / TILE)   /* 32 */
#define TY_N  (H_IMG / TILE)   /* 32 */
#define NTILES (TX_N * TY_N)   /* 1024 */
#define CHUNK 256

#define TWO_PI_F        6.28318530717958647692f
#define LOG2E_F         1.44269504088896340736f
#define LOG2_ALPHA_MIN  -7.99435344f   /* log2(1/255) */
#define ALPHA_MAX_F     0.999f

// Per-gaussian precomputed parameters
__device__ float4 g_P0[NMAX];          // mx, my, A(=0.5*c0), B(=0.5*c2)
__device__ float4 g_P1[NMAX];          // C(=c1), L(=log2(op)), fr, fg
__device__ float  g_FB[NMAX];          // fb
// Per-tile gaussian lists
__device__ int    g_tile_cnt[NTILES];          // zero at load; render re-zeroes
__device__ int    g_tile_list[NTILES][NMAX];   // 8 MB static scratch

// One WARP per gaussian: all lanes redundantly compute params (broadcast loads),
// lane 0 writes them, then all 32 lanes cooperatively test candidate tiles.
__global__ __launch_bounds__(256)
void prep_bin_kernel(const float* __restrict__ xyz,
                     const float* __restrict__ scaling,
                     const float* __restrict__ rot,
                     const float* __restrict__ feat,
                     const float* __restrict__ opac,
                     int N)
{
    int warp = (blockIdx.x * blockDim.x + threadIdx.x) >> 5;
    int lane = threadIdx.x & 31;
    int i = warp;
    if (i >= N) return;

    float theta = (1.0f / (1.0f + expf(-rot[i]))) * TWO_PI_F;
    float s0 = fabsf(scaling[2*i + 0]); s0 *= s0;
    float s1 = fabsf(scaling[2*i + 1]); s1 *= s1;
    float cs = cosf(theta);
    float sn = sinf(theta);

    float a = cs*cs*s0 + sn*sn*s1;
    float b = cs*sn*(s0 - s1);
    float c = sn*sn*s0 + cs*cs*s1;
    float inv_det = 1.0f / (a*c - b*b);
    float c0 =  c * inv_det;
    float c1 = -b * inv_det;
    float c2 =  a * inv_det;

    float mx = 0.5f * ((xyz[2*i + 0] + 1.0f) * (float)W_IMG - 1.0f);
    float my = 0.5f * ((xyz[2*i + 1] + 1.0f) * (float)H_IMG - 1.0f);

    float op = opac[i];
    float L  = log2f(op);                 // alpha = 2^(L - sigma*log2e)
    float lnthr = logf(op * 255.0f);      // contributes iff sigma <= lnthr
    float smax  = fmaxf(s0, s1);          // lambda_max(Sigma) upper bound
    float r2 = (lnthr > 0.0f) ? (2.0f * smax * lnthr) : -1.0f;

    if (lane == 0) {
        g_P0[i] = make_float4(mx, my, 0.5f * c0, 0.5f * c2);
        g_P1[i] = make_float4(c1, L, feat[3*i + 0], feat[3*i + 1]);
        g_FB[i] = feat[3*i + 2];
    }

    if (r2 <= 0.0f) return;
    float r = sqrtf(r2);

    int tx_lo = max(0,        (int)floorf((mx - r) * (1.0f / TILE)));
    int tx_hi = min(TX_N - 1, (int)floorf((mx + r) * (1.0f / TILE)));
    int ty_lo = max(0,        (int)floorf((my - r) * (1.0f / TILE)));
    int ty_hi = min(TY_N - 1, (int)floorf((my + r) * (1.0f / TILE)));
    if (tx_hi < tx_lo || ty_hi < ty_lo) return;

    int w = tx_hi - tx_lo + 1;
    int cand = w * (ty_hi - ty_lo + 1);

    for (int sidx = lane; sidx < cand; sidx += 32) {
        int tx = tx_lo + (sidx % w);
        int ty = ty_lo + (sidx / w);
        float bx0 = (float)(tx * TILE);
        float by0 = (float)(ty * TILE);
        float dxb = fmaxf(0.0f, fmaxf(bx0 - mx, mx - (bx0 + (TILE - 1))));
        float dyb = fmaxf(0.0f, fmaxf(by0 - my, my - (by0 + (TILE - 1))));
        if (fmaf(dxb, dxb, dyb * dyb) <= r2) {
            int t = ty * TX_N + tx;
            int pos = atomicAdd(&g_tile_cnt[t], 1);
            g_tile_list[t][pos] = i;
        }
    }
}

// 256 threads = 4 groups x 64. Params staged in SHARED once per chunk by all
// 256 threads; each group renders the full 16x16 tile as 2x2 quads but
// processes only gaussians j = g, g+4, ... of the chunk (broadcast LDS).
// Partial sums combined via shared memory in fixed order (deterministic).
__global__ __launch_bounds__(256, 4)
void render_kernel(float* __restrict__ out)
{
    __shared__ float4 sP0[CHUNK];
    __shared__ float4 sP1[CHUNK];
    __shared__ float  sFB[CHUNK];
    __shared__ float  s_red[3 * 64 * 13];   // ~10 KB, stride 13 => conflict-free

    const int tid = threadIdx.x;
    const int g   = tid >> 6;        // group 0..3
    const int t64 = tid & 63;
    const int tx  = t64 & 7;         // 0..7
    const int ty  = t64 >> 3;        // 0..7

    const int tile = blockIdx.y * TX_N + blockIdx.x;
    const int px0 = blockIdx.x * TILE + tx;
    const int py0 = blockIdx.y * TILE + ty;
    const float fx0 = (float)px0;
    const float fy0 = (float)py0;

    const int cnt = g_tile_cnt[tile];

    float a00r = 0.0f, a00g = 0.0f, a00b = 0.0f;
    float a10r = 0.0f, a10g = 0.0f, a10b = 0.0f;
    float a01r = 0.0f, a01g = 0.0f, a01b = 0.0f;
    float a11r = 0.0f, a11g = 0.0f, a11b = 0.0f;

    for (int base = 0; base < cnt; base += CHUNK) {
        int m = cnt - base;
        if (m > CHUNK) m = CHUNK;

        // cooperative staging: params loaded from global ONCE per CTA
        if (tid < m) {
            int idx = g_tile_list[tile][base + tid];
            sP0[tid] = g_P0[idx];
            sP1[tid] = g_P1[idx];
            sFB[tid] = g_FB[idx];
        }
        __syncthreads();

        #pragma unroll 2
        for (int j = g; j < m; j += 4) {
            float4 Q0 = sP0[j];
            float4 Q1 = sP1[j];
            float  qb = sFB[j];

            float dx0 = fx0 - Q0.x;
            float dx1 = dx0 + 8.0f;
            float dy0 = fy0 - Q0.y;
            float dy1 = dy0 + 8.0f;

            float adx0 = Q0.z * dx0;            // A*dx (shared per column)
            float adx1 = Q0.z * dx1;
            float bdy0 = (Q0.w * dy0) * dy0;    // B*dy^2 (shared per row)
            float bdy1 = (Q0.w * dy1) * dy1;

            // sigma = (C*dy + A*dx)*dx + B*dy^2 ; arg = L - sigma*log2e
            float t00 = fmaf(Q1.x, dy0, adx0);
            float t10 = fmaf(Q1.x, dy0, adx1);
            float t01 = fmaf(Q1.x, dy1, adx0);
            float t11 = fmaf(Q1.x, dy1, adx1);
            float s00 = fmaf(t00, dx0, bdy0);
            float s10 = fmaf(t10, dx1, bdy0);
            float s01 = fmaf(t01, dx0, bdy1);
            float s11 = fmaf(t11, dx1, bdy1);
            float g00 = fmaf(s00, -LOG2E_F, Q1.y);
            float g10 = fmaf(s10, -LOG2E_F, Q1.y);
            float g01 = fmaf(s01, -LOG2E_F, Q1.y);
            float g11 = fmaf(s11, -LOG2E_F, Q1.y);

            float e00, e10, e01, e11;
            asm("ex2.approx.ftz.f32 %0, %1;" : "=f"(e00) : "f"(g00));
            asm("ex2.approx.ftz.f32 %0, %1;" : "=f"(e10) : "f"(g10));
            asm("ex2.approx.ftz.f32 %0, %1;" : "=f"(e01) : "f"(g01));
            asm("ex2.approx.ftz.f32 %0, %1;" : "=f"(e11) : "f"(g11));
            e00 = fminf(e00, ALPHA_MAX_F);
            e10 = fminf(e10, ALPHA_MAX_F);
            e01 = fminf(e01, ALPHA_MAX_F);
            e11 = fminf(e11, ALPHA_MAX_F);

            if (g00 >= LOG2_ALPHA_MIN) {
                a00r = fmaf(e00, Q1.z, a00r);
                a00g = fmaf(e00, Q1.w, a00g);
                a00b = fmaf(e00, qb,   a00b);
            }
            if (g10 >= LOG2_ALPHA_MIN) {
                a10r = fmaf(e10, Q1.z, a10r);
                a10g = fmaf(e10, Q1.w, a10g);
                a10b = fmaf(e10, qb,   a10b);
            }
            if (g01 >= LOG2_ALPHA_MIN) {
                a01r = fmaf(e01, Q1.z, a01r);
                a01g = fmaf(e01, Q1.w, a01g);
                a01b = fmaf(e01, qb,   a01b);
            }
            if (g11 >= LOG2_ALPHA_MIN) {
                a11r = fmaf(e11, Q1.z, a11r);
                a11g = fmaf(e11, Q1.w, a11g);
                a11b = fmaf(e11, qb,   a11b);
            }
        }
        __syncthreads();
    }

    // combine partial sums: groups 1-3 publish, group 0 adds in fixed order
    if (g > 0) {
        float* dst = &s_red[((g - 1) * 64 + t64) * 13];
        dst[0]  = a00r; dst[1]  = a00g; dst[2]  = a00b;
        dst[3]  = a10r; dst[4]  = a10g; dst[5]  = a10b;
        dst[6]  = a01r; dst[7]  = a01g; dst[8]  = a01b;
        dst[9]  = a11r; dst[10] = a11g; dst[11] = a11b;
    }
    __syncthreads();

    if (g == 0) {
        #pragma unroll
        for (int gg = 0; gg < 3; ++gg) {
            const float* src = &s_red[(gg * 64 + t64) * 13];
            a00r += src[0];  a00g += src[1];  a00b += src[2];
            a10r += src[3];  a10g += src[4];  a10b += src[5];
            a01r += src[6];  a01g += src[7];  a01b += src[8];
            a11r += src[9];  a11g += src[10]; a11b += src[11];
        }

        const int px1 = px0 + 8;
        const int py1 = py0 + 8;
        // out layout: [1, 3, H, W]
        out[(0 * H_IMG + py0) * W_IMG + px0] = fminf(fmaxf(a00r, 0.0f), 1.0f);
        out[(0 * H_IMG + py0) * W_IMG + px1] = fminf(fmaxf(a10r, 0.0f), 1.0f);
        out[(0 * H_IMG + py1) * W_IMG + px0] = fminf(fmaxf(a01r, 0.0f), 1.0f);
        out[(0 * H_IMG + py1) * W_IMG + px1] = fminf(fmaxf(a11r, 0.0f), 1.0f);
        out[(1 * H_IMG + py0) * W_IMG + px0] = fminf(fmaxf(a00g, 0.0f), 1.0f);
        out[(1 * H_IMG + py0) * W_IMG + px1] = fminf(fmaxf(a10g, 0.0f), 1.0f);
        out[(1 * H_IMG + py1) * W_IMG + px0] = fminf(fmaxf(a01g, 0.0f), 1.0f);
        out[(1 * H_IMG + py1) * W_IMG + px1] = fminf(fmaxf(a11g, 0.0f), 1.0f);
        out[(2 * H_IMG + py0) * W_IMG + px0] = fminf(fmaxf(a00b, 0.0f), 1.0f);
        out[(2 * H_IMG + py0) * W_IMG + px1] = fminf(fmaxf(a10b, 0.0f), 1.0f);
        out[(2 * H_IMG + py1) * W_IMG + px0] = fminf(fmaxf(a01b, 0.0f), 1.0f);
        out[(2 * H_IMG + py1) * W_IMG + px1] = fminf(fmaxf(a11b, 0.0f), 1.0f);

        if (t64 == 0) g_tile_cnt[tile] = 0;   // leave zeroed for next launch
    }
}

extern "C" void kernel_launch(void* const* d_in, const int* in_sizes, int n_in,
                              void* d_out, int out_size)
{
    const float* xyz     = (const float*)d_in[0];
    const float* scaling = (const float*)d_in[1];
    const float* rot     = (const float*)d_in[2];
    const float* feat    = (const float*)d_in[3];
    const float* opac    = (const float*)d_in[4];
    float* out = (float*)d_out;

    int N = in_sizes[0] / 2;
    if (N > NMAX) N = NMAX;

    // one warp per gaussian
    prep_bin_kernel<<<(N * 32 + 255) / 256, 256>>>(xyz, scaling, rot, feat, opac, N);

    dim3 grid(TX_N, TY_N);
    render_kernel<<<grid, 256>>>(out);
}